// round 7
// baseline (speedup 1.0000x reference)
#include <cuda_runtime.h>
#include <cuda_bf16.h>

#define BN_EPS 1e-5f

// ---------------- scratch (__device__ globals; no allocation anywhere) ----------------
__device__ float g_swt[1990656];   // [3][64][9][18][64] padded transposed spline weights
__device__ float g_bwt[110592];    // [3][64][9][64] transposed base weights
__device__ float g_fwt[16384];     // [256][64] transposed fuse weights
__device__ float g_ybr[1572864];   // [3][2][64][4096] raw branch conv outputs
__device__ float g_out0[524288];   // [2][64][4096] pre-BN fuse output
__device__ float g_xmean[128];     // [2][64]
__device__ float g_bna[192];       // per (br,o) BN scale
__device__ float g_bnc[192];       // per (br,o) BN shift
__device__ float g_sered[384];     // [br][b][o] spatial mean of relu(bn(y))
__device__ float g_scale[384];     // [br][b][o] SE sigmoid scale
__device__ float g_gpterm[128];    // [b][o] fuse contribution of gp branch
__device__ float g_fa[64];         // fuse BN scale
__device__ float g_fc[64];         // fuse BN shift

__device__ __forceinline__ float sigmoidf_(float v) {
    return __fdividef(1.f, 1.f + __expf(-v));
}

__device__ __forceinline__ float block_reduce(float v, float* sbuf) {
    int tid = threadIdx.x;
    sbuf[tid] = v;
    __syncthreads();
    for (int st = blockDim.x >> 1; st > 0; st >>= 1) {
        if (tid < st) sbuf[tid] += sbuf[tid + st];
        __syncthreads();
    }
    float r = sbuf[0];
    __syncthreads();
    return r;
}

__device__ __forceinline__ float4 fma4(float4 a, float s, float4 b) {
    a.x = fmaf(s, b.x, a.x);
    a.y = fmaf(s, b.y, a.y);
    a.z = fmaf(s, b.z, a.z);
    a.w = fmaf(s, b.w, a.w);
    return a;
}

// ---------------- weight repack ----------------
// g_swt[br][i][k][jj][o]: jj = g+3 with 3 zero-pad rows each side so the 4-row
// gather rows m..m+3 (m in [0, G+5]) never branches on boundary intervals.
__global__ void pack_kernel(const float* __restrict__ bw0, const float* __restrict__ sw0,
                            const float* __restrict__ bw1, const float* __restrict__ sw1,
                            const float* __restrict__ bw2, const float* __restrict__ sw2,
                            const float* __restrict__ fw) {
    int stride = gridDim.x * blockDim.x;
    int t0 = blockIdx.x * blockDim.x + threadIdx.x;
    for (int idx = t0; idx < 1990656; idx += stride) {
        int o = idx & 63;
        int r = idx >> 6;
        int jj = r % 18; r /= 18;
        int k = r % 9;  r /= 9;
        int i = r & 63; int br = r >> 6;
        int G = 3 * (br + 1);
        int g = jj - 3;
        float v = 0.f;
        if (g >= 0 && g < G + 3) {
            const float* sw = (br == 0) ? sw0 : ((br == 1) ? sw1 : sw2);
            v = sw[((o * 64 + i) * 9 + k) * (G + 3) + g];
        }
        g_swt[idx] = v;
    }
    for (int idx = t0; idx < 110592; idx += stride) {
        int o = idx & 63;
        int r = idx >> 6;
        int k = r % 9; r /= 9;
        int i = r & 63; int br = r >> 6;
        const float* bw = (br == 0) ? bw0 : ((br == 1) ? bw1 : bw2);
        g_bwt[idx] = bw[(o * 64 + i) * 9 + k];
    }
    for (int idx = t0; idx < 16384; idx += stride) {
        int o = idx & 63; int ch = idx >> 6;
        g_fwt[idx] = fw[o * 256 + ch];
    }
}

// ---------------- x channel means (gp branch) ----------------
__global__ void xmean_kernel(const float* __restrict__ x) {
    __shared__ float sbuf[128];
    int bi = blockIdx.x;  // b*64 + i
    const float* p = x + bi * 4096;
    float s = 0.f;
    for (int j = threadIdx.x; j < 4096; j += 128) s += p[j];
    s = block_reduce(s, sbuf);
    if (threadIdx.x == 0) g_xmean[bi] = s * (1.f / 4096.f);
}

// ---------------- KAN conv (all 3 branches, one launch) ----------------
// CTA: 32 pixels (b, h, w0..w0+31), 128 threads.
// Per input channel i: stage silu + 4 cardinal-cubic coefficients + interval
// offset per tap into smem, then each lane gathers float4-over-o weight rows
// (coalesced) and FMAs into 4 pixels x 4 o accumulators.
__global__ void __launch_bounds__(128) conv_kernel(const float* __restrict__ x) {
    __shared__ float4 sW4[9][32];
    __shared__ float2 sMeta[9][32];
    int z = blockIdx.z;
    int br = z >> 1, b = z & 1;
    int h = blockIdx.y, w0 = blockIdx.x << 5;
    int d = 6 * (br + 1);
    int G = 3 * (br + 1);
    float invh = 0.5f * (float)G;       // 1/h_grid = G/2
    float s0 = invh + 3.f;              // s = v/h + 1/h + 3
    float smax = (float)(G + 6);
    int tid = threadIdx.x;
    int warpId = tid >> 5, lane = tid & 31;
    int ol = lane & 15, sub = lane >> 4;
    int o4 = ol << 2;                   // this lane covers o4..o4+3
    int pw = ((warpId << 1) | sub) << 2;  // pixel group base (0..28)

    float4 acc[4];
#pragma unroll
    for (int p = 0; p < 4; p++) acc[p] = make_float4(0.f, 0.f, 0.f, 0.f);

    const float* swbr = g_swt + br * 663552;
    const float* bwbr = g_bwt + br * 36864;
    const float* xb = x + b * 64 * 4096;

#pragma unroll 1
    for (int i = 0; i < 64; i++) {
        // ---- stage taps for channel i ----
        for (int j = tid; j < 288; j += 128) {
            int k = j >> 5, p = j & 31;
            int ki = k / 3, kj = k - ki * 3;
            int hh = h + (ki - 1) * d;
            int ww = w0 + p + (kj - 1) * d;
            float v = 0.f;
            if ((unsigned)hh < 64u && (unsigned)ww < 64u)
                v = xb[i * 4096 + hh * 64 + ww];
            float e = __expf(-v);
            float silu = __fdividef(v, 1.f + e);
            float s = fmaf(v, invh, s0);
            float mf = floorf(s);
            float u = s - mf;
            float msk = (s >= 0.f && s < smax) ? (1.f / 6.f) : 0.f;
            int mi = (int)mf;
            mi = min(max(mi, 0), G + 5);
            float u2 = u * u, u3 = u2 * u;
            float omu = 1.f - u;
            float c0 = omu * omu * omu * msk;
            float c3 = u3 * msk;
            float c1 = (3.f * u3 - 6.f * u2 + 4.f) * msk;
            float c2 = (-3.f * u3 + 3.f * u2 + 3.f * u + 1.f) * msk;
            sW4[k][p] = make_float4(c0, c1, c2, c3);
            sMeta[k][p] = make_float2(silu, __int_as_float(mi << 6));
        }
        __syncthreads();

        // ---- accumulate ----
        const float* swi = swbr + i * 10368 + o4;
        const float* bwi = bwbr + i * 576 + o4;
#pragma unroll 1
        for (int k = 0; k < 9; k++) {
            float4 bw4 = *reinterpret_cast<const float4*>(bwi + (k << 6));
            const float* wk = swi + k * 1152;
#pragma unroll
            for (int p = 0; p < 4; p++) {
                float4 w4 = sW4[k][pw + p];
                float2 mt = sMeta[k][pw + p];
                const float* c = wk + __float_as_int(mt.y);
                float4 r0 = *reinterpret_cast<const float4*>(c);
                float4 r1 = *reinterpret_cast<const float4*>(c + 64);
                float4 r2 = *reinterpret_cast<const float4*>(c + 128);
                float4 r3 = *reinterpret_cast<const float4*>(c + 192);
                float4 a = acc[p];
                a = fma4(a, mt.x, bw4);
                a = fma4(a, w4.x, r0);
                a = fma4(a, w4.y, r1);
                a = fma4(a, w4.z, r2);
                a = fma4(a, w4.w, r3);
                acc[p] = a;
            }
        }
        __syncthreads();
    }

    // store: for each of the 4 o's, 4 consecutive pixels -> STG.128
    int hw = h * 64 + w0 + pw;
#pragma unroll
    for (int c = 0; c < 4; c++) {
        float4 v;
        v.x = (c == 0) ? acc[0].x : (c == 1) ? acc[0].y : (c == 2) ? acc[0].z : acc[0].w;
        v.y = (c == 0) ? acc[1].x : (c == 1) ? acc[1].y : (c == 2) ? acc[1].z : acc[1].w;
        v.z = (c == 0) ? acc[2].x : (c == 1) ? acc[2].y : (c == 2) ? acc[2].z : acc[2].w;
        v.w = (c == 0) ? acc[3].x : (c == 1) ? acc[3].y : (c == 2) ? acc[3].z : acc[3].w;
        *reinterpret_cast<float4*>(&g_ybr[(z * 64 + o4 + c) * 4096 + hw]) = v;
    }
}

// ---------------- per-branch BN stats (mean/var over batch+spatial) ----------------
__global__ void bnstats_kernel(const float* __restrict__ g6, const float* __restrict__ bb6,
                               const float* __restrict__ g12, const float* __restrict__ bb12,
                               const float* __restrict__ g18, const float* __restrict__ bb18) {
    __shared__ float sbuf[256];
    int o = blockIdx.x, br = blockIdx.y;
    const float* p0 = g_ybr + ((br * 2 + 0) * 64 + o) * 4096;
    const float* p1 = g_ybr + ((br * 2 + 1) * 64 + o) * 4096;
    float s = 0.f, sq = 0.f;
    for (int j = threadIdx.x; j < 4096; j += 256) {
        float v0 = p0[j], v1 = p1[j];
        s += v0 + v1;
        sq += v0 * v0 + v1 * v1;
    }
    s = block_reduce(s, sbuf);
    sq = block_reduce(sq, sbuf);
    if (threadIdx.x == 0) {
        float mean = s * (1.f / 8192.f);
        float var = sq * (1.f / 8192.f) - mean * mean;
        const float* gg = (br == 0) ? g6 : ((br == 1) ? g12 : g18);
        const float* bb = (br == 0) ? bb6 : ((br == 1) ? bb12 : bb18);
        float a = gg[o] * rsqrtf(var + BN_EPS);
        g_bna[br * 64 + o] = a;
        g_bnc[br * 64 + o] = bb[o] - mean * a;
    }
}

// ---------------- SE spatial reduce: mean over hw of relu(bn(y)) ----------------
__global__ void sered_kernel() {
    __shared__ float sbuf[128];
    int o = blockIdx.x, b = blockIdx.y, br = blockIdx.z;
    const float* p = g_ybr + ((br * 2 + b) * 64 + o) * 4096;
    float a = g_bna[br * 64 + o], c = g_bnc[br * 64 + o];
    float s = 0.f;
    for (int j = threadIdx.x; j < 4096; j += 128)
        s += fmaxf(fmaf(p[j], a, c), 0.f);
    s = block_reduce(s, sbuf);
    if (threadIdx.x == 0) g_sered[(br * 2 + b) * 64 + o] = s * (1.f / 4096.f);
}

// ---------------- SE MLPs + full gp branch + gp fuse term (one CTA) ----------------
__global__ void small_kernel(const float* __restrict__ w1_0, const float* __restrict__ w2_0,
                             const float* __restrict__ w1_1, const float* __restrict__ w2_1,
                             const float* __restrict__ w1_2, const float* __restrict__ w2_2,
                             const float* __restrict__ gpw, const float* __restrict__ gpb,
                             const float* __restrict__ gpg, const float* __restrict__ gpbeta,
                             const float* __restrict__ gpse1, const float* __restrict__ gpse2,
                             const float* __restrict__ fw) {
    __shared__ float sT[24];
    __shared__ float sGp0[128];
    __shared__ float sZ[128];
    __shared__ float sT2[8];
    __shared__ float sGpv[128];
    int tid = threadIdx.x;

    // branch SE hidden layer: t[br][b][j] = relu(sered . w1[j])
    if (tid < 24) {
        int br = tid >> 3;
        int rem = tid & 7;
        int b = rem >> 2, j = rem & 3;
        const float* w1 = (br == 0) ? w1_0 : ((br == 1) ? w1_1 : w1_2);
        float v = 0.f;
        for (int o2 = 0; o2 < 64; o2++) v += g_sered[(br * 2 + b) * 64 + o2] * w1[j * 64 + o2];
        sT[tid] = fmaxf(v, 0.f);
    }
    // gp linear: gp0[b][o] = xmean[b] . gpw[o] + gpb[o]
    {
        int b = tid >> 6, o = tid & 63;
        float v = gpb[o];
        for (int i = 0; i < 64; i++) v += g_xmean[b * 64 + i] * gpw[o * 64 + i];
        sGp0[tid] = v;
    }
    __syncthreads();

    if (tid < 64) {
        int o = tid;
        // branch SE output sigmoids
        for (int br = 0; br < 3; br++) {
            const float* w2 = (br == 0) ? w2_0 : ((br == 1) ? w2_1 : w2_2);
            for (int b = 0; b < 2; b++) {
                float v = 0.f;
                for (int j = 0; j < 4; j++) v += sT[br * 8 + b * 4 + j] * w2[o * 4 + j];
                g_scale[(br * 2 + b) * 64 + o] = sigmoidf_(v);
            }
        }
        // gp BN over batch (B=2, spatial size 1) + relu
        float a0 = sGp0[o], a1 = sGp0[64 + o];
        float m = 0.5f * (a0 + a1);
        float dv = a0 - m;
        float var = dv * dv;
        float rs = gpg[o] * rsqrtf(var + BN_EPS);
        sZ[o]      = fmaxf((a0 - m) * rs + gpbeta[o], 0.f);
        sZ[64 + o] = fmaxf((a1 - m) * rs + gpbeta[o], 0.f);
    }
    __syncthreads();

    if (tid < 8) {
        int b = tid >> 2, j = tid & 3;
        float v = 0.f;
        for (int o2 = 0; o2 < 64; o2++) v += sZ[b * 64 + o2] * gpse1[j * 64 + o2];
        sT2[tid] = fmaxf(v, 0.f);
    }
    __syncthreads();

    {
        int b = tid >> 6, o = tid & 63;
        float v = 0.f;
        for (int j = 0; j < 4; j++) v += sT2[b * 4 + j] * gpse2[o * 4 + j];
        sGpv[tid] = sZ[tid] * sigmoidf_(v);
    }
    __syncthreads();

    // gpterm[b][oo] = sum_i fuse_w[oo][192+i] * gpv[b][i]
    {
        int b = tid >> 6, oo = tid & 63;
        float v = 0.f;
        for (int i = 0; i < 64; i++) v += fw[oo * 256 + 192 + i] * sGpv[b * 64 + i];
        g_gpterm[tid] = v;
    }
}

// ---------------- fuse 1x1 conv over the 192 branch channels ----------------
__global__ void __launch_bounds__(128) fuse_kernel(const float* __restrict__ fuse_b) {
    __shared__ float sCat[192][32];
    int b = blockIdx.z, h = blockIdx.y, w0 = blockIdx.x << 5;
    int tid = threadIdx.x;

    for (int j = tid; j < 192 * 32; j += 128) {
        int ch = j >> 5, p = j & 31;      // ch = br*64 + i
        int br = ch >> 6, i = ch & 63;
        float v = g_ybr[((br * 2 + b) * 64 + i) * 4096 + h * 64 + w0 + p];
        float zz = fmaxf(fmaf(v, g_bna[br * 64 + i], g_bnc[br * 64 + i]), 0.f);
        sCat[ch][p] = zz * g_scale[(br * 2 + b) * 64 + i];
    }
    __syncthreads();

    int warpId = tid >> 5, lane = tid & 31;
    int o = ((warpId & 1) << 5) | lane;
    int ph = warpId >> 1;
    float acc[16];
    float init = g_gpterm[b * 64 + o] + fuse_b[o];
#pragma unroll
    for (int p = 0; p < 16; p++) acc[p] = init;

#pragma unroll 1
    for (int ch = 0; ch < 192; ch++) {
        float fwv = g_fwt[(ch << 6) + o];
#pragma unroll
        for (int p = 0; p < 16; p++)
            acc[p] = fmaf(fwv, sCat[ch][(ph << 4) + p], acc[p]);
    }

    int base = (b * 64 + o) * 4096 + h * 64 + w0 + (ph << 4);
#pragma unroll
    for (int p = 0; p < 16; p++) g_out0[base + p] = acc[p];
}

// ---------------- fuse BN stats ----------------
__global__ void fstats_kernel(const float* __restrict__ fg, const float* __restrict__ fb) {
    __shared__ float sbuf[256];
    int o = blockIdx.x;
    const float* p0 = g_out0 + o * 4096;
    const float* p1 = g_out0 + (64 + o) * 4096;
    float s = 0.f, sq = 0.f;
    for (int j = threadIdx.x; j < 4096; j += 256) {
        float v0 = p0[j], v1 = p1[j];
        s += v0 + v1;
        sq += v0 * v0 + v1 * v1;
    }
    s = block_reduce(s, sbuf);
    sq = block_reduce(sq, sbuf);
    if (threadIdx.x == 0) {
        float mean = s * (1.f / 8192.f);
        float var = sq * (1.f / 8192.f) - mean * mean;
        float a = fg[o] * rsqrtf(var + BN_EPS);
        g_fa[o] = a;
        g_fc[o] = fb[o] - mean * a;
    }
}

// ---------------- final elementwise: relu(bn(fuse_out)) ----------------
__global__ void final_kernel(float* __restrict__ out) {
    int idx = blockIdx.x * blockDim.x + threadIdx.x;
    if (idx >= 524288) return;
    int o = (idx >> 12) & 63;
    out[idx] = fmaxf(fmaf(g_out0[idx], g_fa[o], g_fc[o]), 0.f);
}

// ---------------- launch ----------------
extern "C" void kernel_launch(void* const* d_in, const int* in_sizes, int n_in,
                              void* d_out, int out_size) {
    const float* x       = (const float*)d_in[0];
    const float* bw6     = (const float*)d_in[1];
    const float* sw6     = (const float*)d_in[2];
    const float* bn6_g   = (const float*)d_in[3];
    const float* bn6_b   = (const float*)d_in[4];
    const float* se6_w1  = (const float*)d_in[5];
    const float* se6_w2  = (const float*)d_in[6];
    const float* bw12    = (const float*)d_in[7];
    const float* sw12    = (const float*)d_in[8];
    const float* bn12_g  = (const float*)d_in[9];
    const float* bn12_b  = (const float*)d_in[10];
    const float* se12_w1 = (const float*)d_in[11];
    const float* se12_w2 = (const float*)d_in[12];
    const float* bw18    = (const float*)d_in[13];
    const float* sw18    = (const float*)d_in[14];
    const float* bn18_g  = (const float*)d_in[15];
    const float* bn18_b  = (const float*)d_in[16];
    const float* se18_w1 = (const float*)d_in[17];
    const float* se18_w2 = (const float*)d_in[18];
    const float* gp_w    = (const float*)d_in[19];
    const float* gp_b    = (const float*)d_in[20];
    const float* gp_bn_g = (const float*)d_in[21];
    const float* gp_bn_b = (const float*)d_in[22];
    const float* gp_se1  = (const float*)d_in[23];
    const float* gp_se2  = (const float*)d_in[24];
    const float* fuse_w  = (const float*)d_in[25];
    const float* fuse_b  = (const float*)d_in[26];
    const float* fbn_g   = (const float*)d_in[27];
    const float* fbn_b   = (const float*)d_in[28];
    float* out = (float*)d_out;

    pack_kernel<<<512, 256>>>(bw6, sw6, bw12, sw12, bw18, sw18, fuse_w);
    xmean_kernel<<<128, 128>>>(x);
    conv_kernel<<<dim3(2, 64, 6), 128>>>(x);
    bnstats_kernel<<<dim3(64, 3), 256>>>(bn6_g, bn6_b, bn12_g, bn12_b, bn18_g, bn18_b);
    sered_kernel<<<dim3(64, 2, 3), 128>>>();
    small_kernel<<<1, 128>>>(se6_w1, se6_w2, se12_w1, se12_w2, se18_w1, se18_w2,
                             gp_w, gp_b, gp_bn_g, gp_bn_b, gp_se1, gp_se2, fuse_w);
    fuse_kernel<<<dim3(2, 64, 2), 128>>>(fuse_b);
    fstats_kernel<<<64, 256>>>(fbn_g, fbn_b);
    final_kernel<<<2048, 256>>>(out);
}

// round 8
// speedup vs baseline: 1.1265x; 1.1265x over previous
#include <cuda_runtime.h>
#include <cuda_fp16.h>
#include <cuda_bf16.h>

#define BN_EPS 1e-5f
typedef unsigned long long ull;

// ---------------- scratch (__device__ globals; no allocation anywhere) ----------------
__device__ __align__(16) __half g_swh[1990656]; // [3][64][9][18][64] padded spline weights, fp16
__device__ __align__(16) float g_bwt[110592];   // [3][64][9][64] transposed base weights
__device__ __align__(16) float g_fwt[16384];    // [256][64] transposed fuse weights
__device__ __align__(16) float g_ybr[1572864];  // [3][2][64][4096] raw branch conv outputs
__device__ __align__(16) float g_out0[524288];  // [2][64][4096] pre-BN fuse output
__device__ float g_xmean[128];     // [2][64]
__device__ float g_bna[192];       // per (br,o) BN scale
__device__ float g_bnc[192];       // per (br,o) BN shift
__device__ float g_sered[384];     // [br][b][o] spatial mean of relu(bn(y))
__device__ float g_scale[384];     // [br][b][o] SE sigmoid scale
__device__ float g_gpterm[128];    // [b][o] fuse contribution of gp branch
__device__ float g_fa[64];         // fuse BN scale
__device__ float g_fc[64];         // fuse BN shift

__device__ __forceinline__ float sigmoidf_(float v) {
    return __fdividef(1.f, 1.f + __expf(-v));
}

__device__ __forceinline__ float block_reduce(float v, float* sbuf) {
    int tid = threadIdx.x;
    sbuf[tid] = v;
    __syncthreads();
    for (int st = blockDim.x >> 1; st > 0; st >>= 1) {
        if (tid < st) sbuf[tid] += sbuf[tid + st];
        __syncthreads();
    }
    float r = sbuf[0];
    __syncthreads();
    return r;
}

// ---- packed f32x2 helpers (sm_100+: fma.rn.f32x2) ----
__device__ __forceinline__ ull pack2(float x, float y) {
    ull r;
    asm("mov.b64 %0, {%1, %2};" : "=l"(r) : "f"(x), "f"(y));
    return r;
}
__device__ __forceinline__ float2 unpack2(ull v) {
    float2 r;
    asm("mov.b64 {%0, %1}, %2;" : "=f"(r.x), "=f"(r.y) : "l"(v));
    return r;
}
__device__ __forceinline__ ull ffma2u(ull a, ull b, ull c) {
    ull d;
    asm("fma.rn.f32x2 %0, %1, %2, %3;" : "=l"(d) : "l"(a), "l"(b), "l"(c));
    return d;
}
__device__ __forceinline__ ull h2p(__half2 h) {
    float2 f = __half22float2(h);
    return pack2(f.x, f.y);
}

// ---------------- weight repack ----------------
// g_swh[br][i][k][jj][o]: jj = g+3 with 3 zero-pad rows each side so the 4-row
// gather rows m..m+3 (m in [0, G+5]) never branches on boundary intervals.
__global__ void pack_kernel(const float* __restrict__ bw0, const float* __restrict__ sw0,
                            const float* __restrict__ bw1, const float* __restrict__ sw1,
                            const float* __restrict__ bw2, const float* __restrict__ sw2,
                            const float* __restrict__ fw) {
    int stride = gridDim.x * blockDim.x;
    int t0 = blockIdx.x * blockDim.x + threadIdx.x;
    for (int idx = t0; idx < 1990656; idx += stride) {
        int o = idx & 63;
        int r = idx >> 6;
        int jj = r % 18; r /= 18;
        int k = r % 9;  r /= 9;
        int i = r & 63; int br = r >> 6;
        int G = 3 * (br + 1);
        int g = jj - 3;
        float v = 0.f;
        if (g >= 0 && g < G + 3) {
            const float* sw = (br == 0) ? sw0 : ((br == 1) ? sw1 : sw2);
            v = sw[((o * 64 + i) * 9 + k) * (G + 3) + g];
        }
        g_swh[idx] = __float2half(v);
    }
    for (int idx = t0; idx < 110592; idx += stride) {
        int o = idx & 63;
        int r = idx >> 6;
        int k = r % 9; r /= 9;
        int i = r & 63; int br = r >> 6;
        const float* bw = (br == 0) ? bw0 : ((br == 1) ? bw1 : bw2);
        g_bwt[idx] = bw[(o * 64 + i) * 9 + k];
    }
    for (int idx = t0; idx < 16384; idx += stride) {
        int o = idx & 63; int ch = idx >> 6;
        g_fwt[idx] = fw[o * 256 + ch];
    }
}

// ---------------- x channel means (gp branch) ----------------
__global__ void xmean_kernel(const float* __restrict__ x) {
    __shared__ float sbuf[128];
    int bi = blockIdx.x;  // b*64 + i
    const float4* p = (const float4*)(x + bi * 4096);
    float s = 0.f;
    for (int j = threadIdx.x; j < 1024; j += 128) {
        float4 v = p[j];
        s += (v.x + v.y) + (v.z + v.w);
    }
    s = block_reduce(s, sbuf);
    if (threadIdx.x == 0) g_xmean[bi] = s * (1.f / 4096.f);
}

// ---------------- KAN conv (all 3 branches, one launch) ----------------
// CTA: 32 pixels (b, h, w0..w0+31), 128 threads.
// lane = (pxs:2)(og:3): og covers o = og*8..og*8+7 (one LDG.128 of fp16 per row),
// 8 consecutive lanes share a pixel -> 128B coalesced row loads.
// Thread handles 2 pixels x 8 outputs, accumulated as packed f32x2 via FFMA2.
__global__ void __launch_bounds__(128, 5) conv_kernel(const float* __restrict__ x) {
    __shared__ float4 sC[9][32];   // cardinal-cubic coefficients (pre-scaled, masked)
    __shared__ float2 sM[9][32];   // (silu, row byte-offset as int bits)
    int z = blockIdx.z;
    int br = z >> 1, b = z & 1;
    int h = blockIdx.y, w0 = blockIdx.x << 5;
    int d = 6 * (br + 1);
    int G = 3 * (br + 1);
    float invh = 0.5f * (float)G;       // 1/h_grid = G/2
    float s0 = invh + 3.f;              // s = v/h + 1/h + 3
    float smax = (float)(G + 6);
    int tid = threadIdx.x;
    int warpId = tid >> 5, lane = tid & 31;
    int og = lane & 7, pxs = lane >> 3;
    int px0 = (warpId << 2) | pxs;      // second pixel = px0 + 16
    int og16 = og << 4;                 // byte offset within a 128B row
    int og8 = og << 3;

    ull acc[2][4];
#pragma unroll
    for (int p = 0; p < 2; p++)
#pragma unroll
        for (int j = 0; j < 4; j++) acc[p][j] = 0ull;

    const char* swbr = (const char*)g_swh + br * 1327104;  // 663552 halves * 2B
    const float* bwbr = g_bwt + br * 36864;
    const float* xb = x + b * 64 * 4096;

#pragma unroll 1
    for (int i = 0; i < 64; i++) {
        // ---- stage taps for channel i ----
        for (int j = tid; j < 288; j += 128) {
            int k = j >> 5, p = j & 31;
            int ki = k / 3, kj = k - ki * 3;
            int hh = h + (ki - 1) * d;
            int ww = w0 + p + (kj - 1) * d;
            float v = 0.f;
            if ((unsigned)hh < 64u && (unsigned)ww < 64u)
                v = xb[i * 4096 + hh * 64 + ww];
            float e = __expf(-v);
            float silu = __fdividef(v, 1.f + e);
            float s = fmaf(v, invh, s0);
            float mf = floorf(s);
            float u = s - mf;
            float msk = (s >= 0.f && s < smax) ? (1.f / 6.f) : 0.f;
            int mi = (int)mf;
            mi = min(max(mi, 0), G + 5);
            float u2 = u * u, u3 = u2 * u;
            float omu = 1.f - u;
            float c0 = omu * omu * omu * msk;
            float c3 = u3 * msk;
            float c1 = (3.f * u3 - 6.f * u2 + 4.f) * msk;
            float c2 = (-3.f * u3 + 3.f * u2 + 3.f * u + 1.f) * msk;
            sC[k][p] = make_float4(c0, c1, c2, c3);
            sM[k][p] = make_float2(silu, __int_as_float(mi << 7));  // mi*128 bytes
        }
        __syncthreads();

        const char* swi = swbr + i * 20736;          // 9*18*64*2 bytes
        const float* bwi = bwbr + i * 576 + og8;
#pragma unroll 1
        for (int k = 0; k < 9; k++) {
            float4 b0 = *(const float4*)(bwi + (k << 6));
            float4 b1 = *(const float4*)(bwi + (k << 6) + 4);
            ull bw[4] = {pack2(b0.x, b0.y), pack2(b0.z, b0.w),
                         pack2(b1.x, b1.y), pack2(b1.z, b1.w)};
            const char* swk = swi + k * 2304;        // 18*64*2 bytes
#pragma unroll
            for (int pp = 0; pp < 2; pp++) {
                int px = px0 + (pp << 4);
                float4 cf = sC[k][px];
                float2 mt = sM[k][px];
                const char* wp = swk + __float_as_int(mt.y) + og16;
                uint4 r0 = *(const uint4*)(wp);
                uint4 r1 = *(const uint4*)(wp + 128);
                uint4 r2 = *(const uint4*)(wp + 256);
                uint4 r3 = *(const uint4*)(wp + 384);
                ull sil = pack2(mt.x, mt.x);
                ull c0 = pack2(cf.x, cf.x);
                ull c1 = pack2(cf.y, cf.y);
                ull c2 = pack2(cf.z, cf.z);
                ull c3 = pack2(cf.w, cf.w);
                const __half2* h0 = (const __half2*)&r0;
                const __half2* h1 = (const __half2*)&r1;
                const __half2* h2 = (const __half2*)&r2;
                const __half2* h3 = (const __half2*)&r3;
#pragma unroll
                for (int j = 0; j < 4; j++) {
                    ull a = acc[pp][j];
                    a = ffma2u(sil, bw[j], a);
                    a = ffma2u(c0, h2p(h0[j]), a);
                    a = ffma2u(c1, h2p(h1[j]), a);
                    a = ffma2u(c2, h2p(h2[j]), a);
                    a = ffma2u(c3, h2p(h3[j]), a);
                    acc[pp][j] = a;
                }
            }
        }
        __syncthreads();
    }

    // store: 2 px x 8 o scalar stores (negligible vs inner-loop traffic)
    int zbase = z * 64;
#pragma unroll
    for (int pp = 0; pp < 2; pp++) {
        int hw = h * 64 + w0 + px0 + (pp << 4);
#pragma unroll
        for (int j = 0; j < 4; j++) {
            float2 v = unpack2(acc[pp][j]);
            int o = og8 + (j << 1);
            g_ybr[(zbase + o) * 4096 + hw] = v.x;
            g_ybr[(zbase + o + 1) * 4096 + hw] = v.y;
        }
    }
}

// ---------------- per-branch BN stats (mean/var over batch+spatial) ----------------
__global__ void bnstats_kernel(const float* __restrict__ g6, const float* __restrict__ bb6,
                               const float* __restrict__ g12, const float* __restrict__ bb12,
                               const float* __restrict__ g18, const float* __restrict__ bb18) {
    __shared__ float sbuf[256];
    int o = blockIdx.x, br = blockIdx.y;
    const float4* p0 = (const float4*)(g_ybr + ((br * 2 + 0) * 64 + o) * 4096);
    const float4* p1 = (const float4*)(g_ybr + ((br * 2 + 1) * 64 + o) * 4096);
    float s = 0.f, sq = 0.f;
    for (int j = threadIdx.x; j < 1024; j += 256) {
        float4 v0 = p0[j], v1 = p1[j];
        s += (v0.x + v0.y) + (v0.z + v0.w) + (v1.x + v1.y) + (v1.z + v1.w);
        sq += v0.x * v0.x + v0.y * v0.y + v0.z * v0.z + v0.w * v0.w
            + v1.x * v1.x + v1.y * v1.y + v1.z * v1.z + v1.w * v1.w;
    }
    s = block_reduce(s, sbuf);
    sq = block_reduce(sq, sbuf);
    if (threadIdx.x == 0) {
        float mean = s * (1.f / 8192.f);
        float var = sq * (1.f / 8192.f) - mean * mean;
        const float* gg = (br == 0) ? g6 : ((br == 1) ? g12 : g18);
        const float* bb = (br == 0) ? bb6 : ((br == 1) ? bb12 : bb18);
        float a = gg[o] * rsqrtf(var + BN_EPS);
        g_bna[br * 64 + o] = a;
        g_bnc[br * 64 + o] = bb[o] - mean * a;
    }
}

// ---------------- SE spatial reduce: mean over hw of relu(bn(y)) ----------------
__global__ void sered_kernel() {
    __shared__ float sbuf[128];
    int o = blockIdx.x, b = blockIdx.y, br = blockIdx.z;
    const float4* p = (const float4*)(g_ybr + ((br * 2 + b) * 64 + o) * 4096);
    float a = g_bna[br * 64 + o], c = g_bnc[br * 64 + o];
    float s = 0.f;
    for (int j = threadIdx.x; j < 1024; j += 128) {
        float4 v = p[j];
        s += fmaxf(fmaf(v.x, a, c), 0.f) + fmaxf(fmaf(v.y, a, c), 0.f)
           + fmaxf(fmaf(v.z, a, c), 0.f) + fmaxf(fmaf(v.w, a, c), 0.f);
    }
    s = block_reduce(s, sbuf);
    if (threadIdx.x == 0) g_sered[(br * 2 + b) * 64 + o] = s * (1.f / 4096.f);
}

// ---------------- SE MLPs + full gp branch + gp fuse term (one CTA) ----------------
__global__ void small_kernel(const float* __restrict__ w1_0, const float* __restrict__ w2_0,
                             const float* __restrict__ w1_1, const float* __restrict__ w2_1,
                             const float* __restrict__ w1_2, const float* __restrict__ w2_2,
                             const float* __restrict__ gpw, const float* __restrict__ gpb,
                             const float* __restrict__ gpg, const float* __restrict__ gpbeta,
                             const float* __restrict__ gpse1, const float* __restrict__ gpse2,
                             const float* __restrict__ fw) {
    __shared__ float sT[24];
    __shared__ float sGp0[128];
    __shared__ float sZ[128];
    __shared__ float sT2[8];
    __shared__ float sGpv[128];
    int tid = threadIdx.x;

    if (tid < 24) {
        int br = tid >> 3;
        int rem = tid & 7;
        int b = rem >> 2, j = rem & 3;
        const float* w1 = (br == 0) ? w1_0 : ((br == 1) ? w1_1 : w1_2);
        float v = 0.f;
        for (int o2 = 0; o2 < 64; o2++) v += g_sered[(br * 2 + b) * 64 + o2] * w1[j * 64 + o2];
        sT[tid] = fmaxf(v, 0.f);
    }
    {
        int b = tid >> 6, o = tid & 63;
        float v = gpb[o];
        for (int i = 0; i < 64; i++) v += g_xmean[b * 64 + i] * gpw[o * 64 + i];
        sGp0[tid] = v;
    }
    __syncthreads();

    if (tid < 64) {
        int o = tid;
        for (int br = 0; br < 3; br++) {
            const float* w2 = (br == 0) ? w2_0 : ((br == 1) ? w2_1 : w2_2);
            for (int b = 0; b < 2; b++) {
                float v = 0.f;
                for (int j = 0; j < 4; j++) v += sT[br * 8 + b * 4 + j] * w2[o * 4 + j];
                g_scale[(br * 2 + b) * 64 + o] = sigmoidf_(v);
            }
        }
        float a0 = sGp0[o], a1 = sGp0[64 + o];
        float m = 0.5f * (a0 + a1);
        float dv = a0 - m;
        float var = dv * dv;
        float rs = gpg[o] * rsqrtf(var + BN_EPS);
        sZ[o]      = fmaxf((a0 - m) * rs + gpbeta[o], 0.f);
        sZ[64 + o] = fmaxf((a1 - m) * rs + gpbeta[o], 0.f);
    }
    __syncthreads();

    if (tid < 8) {
        int b = tid >> 2, j = tid & 3;
        float v = 0.f;
        for (int o2 = 0; o2 < 64; o2++) v += sZ[b * 64 + o2] * gpse1[j * 64 + o2];
        sT2[tid] = fmaxf(v, 0.f);
    }
    __syncthreads();

    {
        int b = tid >> 6, o = tid & 63;
        float v = 0.f;
        for (int j = 0; j < 4; j++) v += sT2[b * 4 + j] * gpse2[o * 4 + j];
        sGpv[tid] = sZ[tid] * sigmoidf_(v);
    }
    __syncthreads();

    {
        int b = tid >> 6, oo = tid & 63;
        float v = 0.f;
        for (int i = 0; i < 64; i++) v += fw[oo * 256 + 192 + i] * sGpv[b * 64 + i];
        g_gpterm[tid] = v;
    }
}

// ---------------- fuse 1x1 conv over the 192 branch channels ----------------
__global__ void __launch_bounds__(128) fuse_kernel(const float* __restrict__ fuse_b) {
    __shared__ float sCat[192][32];
    int b = blockIdx.z, h = blockIdx.y, w0 = blockIdx.x << 5;
    int tid = threadIdx.x;

    for (int j = tid; j < 1536; j += 128) {   // 192 ch x 8 float4
        int ch = j >> 3, p4 = (j & 7) << 2;
        int br = ch >> 6, i = ch & 63;
        float4 v = *(const float4*)(g_ybr + ((br * 2 + b) * 64 + i) * 4096 + h * 64 + w0 + p4);
        float a = g_bna[br * 64 + i], c = g_bnc[br * 64 + i];
        float sc = g_scale[(br * 2 + b) * 64 + i];
        float4 r;
        r.x = fmaxf(fmaf(v.x, a, c), 0.f) * sc;
        r.y = fmaxf(fmaf(v.y, a, c), 0.f) * sc;
        r.z = fmaxf(fmaf(v.z, a, c), 0.f) * sc;
        r.w = fmaxf(fmaf(v.w, a, c), 0.f) * sc;
        *(float4*)&sCat[ch][p4] = r;
    }
    __syncthreads();

    int warpId = tid >> 5, lane = tid & 31;
    int o = ((warpId & 1) << 5) | lane;
    int ph = warpId >> 1;
    float acc[16];
    float init = g_gpterm[b * 64 + o] + fuse_b[o];
#pragma unroll
    for (int p = 0; p < 16; p++) acc[p] = init;

#pragma unroll 1
    for (int ch = 0; ch < 192; ch++) {
        float fwv = g_fwt[(ch << 6) + o];
#pragma unroll
        for (int p = 0; p < 16; p++)
            acc[p] = fmaf(fwv, sCat[ch][(ph << 4) + p], acc[p]);
    }

    int base = (b * 64 + o) * 4096 + h * 64 + w0 + (ph << 4);
#pragma unroll
    for (int p = 0; p < 16; p++) g_out0[base + p] = acc[p];
}

// ---------------- fuse BN stats ----------------
__global__ void fstats_kernel(const float* __restrict__ fg, const float* __restrict__ fb) {
    __shared__ float sbuf[256];
    int o = blockIdx.x;
    const float4* p0 = (const float4*)(g_out0 + o * 4096);
    const float4* p1 = (const float4*)(g_out0 + (64 + o) * 4096);
    float s = 0.f, sq = 0.f;
    for (int j = threadIdx.x; j < 1024; j += 256) {
        float4 v0 = p0[j], v1 = p1[j];
        s += (v0.x + v0.y) + (v0.z + v0.w) + (v1.x + v1.y) + (v1.z + v1.w);
        sq += v0.x * v0.x + v0.y * v0.y + v0.z * v0.z + v0.w * v0.w
            + v1.x * v1.x + v1.y * v1.y + v1.z * v1.z + v1.w * v1.w;
    }
    s = block_reduce(s, sbuf);
    sq = block_reduce(sq, sbuf);
    if (threadIdx.x == 0) {
        float mean = s * (1.f / 8192.f);
        float var = sq * (1.f / 8192.f) - mean * mean;
        float a = fg[o] * rsqrtf(var + BN_EPS);
        g_fa[o] = a;
        g_fc[o] = fb[o] - mean * a;
    }
}

// ---------------- final elementwise: relu(bn(fuse_out)) ----------------
__global__ void final_kernel(float* __restrict__ out) {
    int idx = blockIdx.x * blockDim.x + threadIdx.x;
    if (idx >= 131072) return;
    int o = (idx >> 10) & 63;
    float a = g_fa[o], c = g_fc[o];
    float4 v = ((const float4*)g_out0)[idx];
    float4 r;
    r.x = fmaxf(fmaf(v.x, a, c), 0.f);
    r.y = fmaxf(fmaf(v.y, a, c), 0.f);
    r.z = fmaxf(fmaf(v.z, a, c), 0.f);
    r.w = fmaxf(fmaf(v.w, a, c), 0.f);
    ((float4*)out)[idx] = r;
}

// ---------------- launch ----------------
extern "C" void kernel_launch(void* const* d_in, const int* in_sizes, int n_in,
                              void* d_out, int out_size) {
    const float* x       = (const float*)d_in[0];
    const float* bw6     = (const float*)d_in[1];
    const float* sw6     = (const float*)d_in[2];
    const float* bn6_g   = (const float*)d_in[3];
    const float* bn6_b   = (const float*)d_in[4];
    const float* se6_w1  = (const float*)d_in[5];
    const float* se6_w2  = (const float*)d_in[6];
    const float* bw12    = (const float*)d_in[7];
    const float* sw12    = (const float*)d_in[8];
    const float* bn12_g  = (const float*)d_in[9];
    const float* bn12_b  = (const float*)d_in[10];
    const float* se12_w1 = (const float*)d_in[11];
    const float* se12_w2 = (const float*)d_in[12];
    const float* bw18    = (const float*)d_in[13];
    const float* sw18    = (const float*)d_in[14];
    const float* bn18_g  = (const float*)d_in[15];
    const float* bn18_b  = (const float*)d_in[16];
    const float* se18_w1 = (const float*)d_in[17];
    const float* se18_w2 = (const float*)d_in[18];
    const float* gp_w    = (const float*)d_in[19];
    const float* gp_b    = (const float*)d_in[20];
    const float* gp_bn_g = (const float*)d_in[21];
    const float* gp_bn_b = (const float*)d_in[22];
    const float* gp_se1  = (const float*)d_in[23];
    const float* gp_se2  = (const float*)d_in[24];
    const float* fuse_w  = (const float*)d_in[25];
    const float* fuse_b  = (const float*)d_in[26];
    const float* fbn_g   = (const float*)d_in[27];
    const float* fbn_b   = (const float*)d_in[28];
    float* out = (float*)d_out;

    pack_kernel<<<512, 256>>>(bw6, sw6, bw12, sw12, bw18, sw18, fuse_w);
    xmean_kernel<<<128, 128>>>(x);
    conv_kernel<<<dim3(2, 64, 6), 128>>>(x);
    bnstats_kernel<<<dim3(64, 3), 256>>>(bn6_g, bn6_b, bn12_g, bn12_b, bn18_g, bn18_b);
    sered_kernel<<<dim3(64, 2, 3), 128>>>();
    small_kernel<<<1, 128>>>(se6_w1, se6_w2, se12_w1, se12_w2, se18_w1, se18_w2,
                             gp_w, gp_b, gp_bn_g, gp_bn_b, gp_se1, gp_se2, fuse_w);
    fuse_kernel<<<dim3(2, 64, 2), 128>>>(fuse_b);
    fstats_kernel<<<64, 256>>>(fbn_g, fbn_b);
    final_kernel<<<512, 256>>>(out);
}

// round 11
// speedup vs baseline: 1.1715x; 1.0400x over previous
#include <cuda_runtime.h>
#include <cuda_fp16.h>
#include <cuda_bf16.h>

#define BN_EPS 1e-5f
typedef unsigned long long ull;

// ---------------- scratch (__device__ globals; no allocation anywhere) ----------------
__device__ __align__(16) __half g_swh[1990656]; // [3][64][9][18][64] padded spline weights, fp16
__device__ __align__(16) float g_bwt[110592];   // [3][64][9][64] transposed base weights
__device__ __align__(16) float g_fwt[16384];    // [256][64] transposed fuse weights
__device__ __align__(16) float g_ybr[1572864];  // [3][2][64][4096] raw branch conv outputs
__device__ __align__(16) float g_out0[524288];  // [2][64][4096] pre-BN fuse output
__device__ float g_xmean[128];     // [2][64]
__device__ float g_bna[192];       // per (br,o) BN scale
__device__ float g_bnc[192];       // per (br,o) BN shift
__device__ float g_sered[384];     // [br][b][o] spatial mean of relu(bn(y))
__device__ float g_scale[384];     // [br][b][o] SE sigmoid scale
__device__ float g_gpterm[128];    // [b][o] fuse contribution of gp branch
__device__ float g_fa[64];         // fuse BN scale
__device__ float g_fc[64];         // fuse BN shift

__device__ __forceinline__ float sigmoidf_(float v) {
    return __fdividef(1.f, 1.f + __expf(-v));
}

__device__ __forceinline__ float block_reduce(float v, float* sbuf) {
    int tid = threadIdx.x;
    sbuf[tid] = v;
    __syncthreads();
    for (int st = blockDim.x >> 1; st > 0; st >>= 1) {
        if (tid < st) sbuf[tid] += sbuf[tid + st];
        __syncthreads();
    }
    float r = sbuf[0];
    __syncthreads();
    return r;
}

// ---- packed f32x2 helpers (sm_100+: fma.rn.f32x2 / add.rn.f32x2) ----
__device__ __forceinline__ float2 unpack2(ull v) {
    float2 r;
    asm("mov.b64 {%0, %1}, %2;" : "=f"(r.x), "=f"(r.y) : "l"(v));
    return r;
}
__device__ __forceinline__ ull ffma2u(ull a, ull b, ull c) {  // a*b + c
    ull d;
    asm("fma.rn.f32x2 %0, %1, %2, %3;" : "=l"(d) : "l"(a), "l"(b), "l"(c));
    return d;
}
__device__ __forceinline__ ull fadd2u(ull a, ull b) {
    ull d;
    asm("add.rn.f32x2 %0, %1, %2;" : "=l"(d) : "l"(a), "l"(b));
    return d;
}
// half2 (as u32) -> packed f32x2 pair: 2x F2F, movs elided by ptxas regalloc
__device__ __forceinline__ ull h2f2(unsigned hv) {
    ull r;
    asm("{\n\t"
        ".reg .b16 l, h;\n\t"
        ".reg .f32 fl, fh;\n\t"
        "mov.b32 {l, h}, %1;\n\t"
        "cvt.f32.f16 fl, l;\n\t"
        "cvt.f32.f16 fh, h;\n\t"
        "mov.b64 %0, {fl, fh};\n\t"
        "}" : "=l"(r) : "r"(hv));
    return r;
}
__device__ __forceinline__ unsigned h2u(__half2 h) {
    return *reinterpret_cast<unsigned*>(&h);
}
__device__ __forceinline__ __half2 u2h(unsigned u) {
    __half2 h;
    *reinterpret_cast<unsigned*>(&h) = u;
    return h;
}

// ---------------- weight repack ----------------
// g_swh[br][i][k][jj][o]: jj = g+3 with 3 zero-pad rows each side so the 4-row
// gather rows m..m+3 (m in [0, G+5]) never branches on boundary intervals.
__global__ void pack_kernel(const float* __restrict__ bw0, const float* __restrict__ sw0,
                            const float* __restrict__ bw1, const float* __restrict__ sw1,
                            const float* __restrict__ bw2, const float* __restrict__ sw2,
                            const float* __restrict__ fw) {
    int stride = gridDim.x * blockDim.x;
    int t0 = blockIdx.x * blockDim.x + threadIdx.x;
    for (int idx = t0; idx < 1990656; idx += stride) {
        int o = idx & 63;
        int r = idx >> 6;
        int jj = r % 18; r /= 18;
        int k = r % 9;  r /= 9;
        int i = r & 63; int br = r >> 6;
        int G = 3 * (br + 1);
        int g = jj - 3;
        float v = 0.f;
        if (g >= 0 && g < G + 3) {
            const float* sw = (br == 0) ? sw0 : ((br == 1) ? sw1 : sw2);
            v = sw[((o * 64 + i) * 9 + k) * (G + 3) + g];
        }
        g_swh[idx] = __float2half(v);
    }
    for (int idx = t0; idx < 110592; idx += stride) {
        int o = idx & 63;
        int r = idx >> 6;
        int k = r % 9; r /= 9;
        int i = r & 63; int br = r >> 6;
        const float* bw = (br == 0) ? bw0 : ((br == 1) ? bw1 : bw2);
        g_bwt[idx] = bw[(o * 64 + i) * 9 + k];
    }
    for (int idx = t0; idx < 16384; idx += stride) {
        int o = idx & 63; int ch = idx >> 6;
        g_fwt[idx] = fw[o * 256 + ch];
    }
}

// ---------------- x channel means (gp branch) ----------------
__global__ void xmean_kernel(const float* __restrict__ x) {
    __shared__ float sbuf[128];
    int bi = blockIdx.x;  // b*64 + i
    const float4* p = (const float4*)(x + bi * 4096);
    float s = 0.f;
    for (int j = threadIdx.x; j < 1024; j += 128) {
        float4 v = p[j];
        s += (v.x + v.y) + (v.z + v.w);
    }
    s = block_reduce(s, sbuf);
    if (threadIdx.x == 0) g_xmean[bi] = s * (1.f / 4096.f);
}

// ---------------- KAN conv (all 3 branches, one launch) ----------------
// CTA: 32 pixels (b, h, w0..w0+31), 128 threads.
// lane = (pxs:2)(og:3): og covers o = og*8..og*8+7 (one LDG.128 of fp16 per row),
// 8 consecutive lanes share a pixel -> 128B coalesced row loads (1 line per px).
// Spline 4-row gather product runs natively in HFMA2; one half2->f32x2 convert
// per o-pair; base term + fold in packed f32x2. No per-element converts/packs.
__global__ void __launch_bounds__(128, 5) conv_kernel(const float* __restrict__ x) {
    __shared__ float2 sSil[9][32];   // (silu, silu) duplicated pair
    __shared__ int    sOff[9][32];   // row byte offset = mi*128
    __shared__ uint4  sCh[9][32];    // c0..c3 as duplicated half2 (1/6+mask folded)
    int z = blockIdx.z;
    int br = z >> 1, b = z & 1;
    int h = blockIdx.y, w0 = blockIdx.x << 5;
    int d = 6 * (br + 1);
    int G = 3 * (br + 1);
    float invh = 0.5f * (float)G;       // 1/h_grid = G/2
    float s0 = invh + 3.f;              // s = v/h + 1/h + 3
    float smax = (float)(G + 6);
    int tid = threadIdx.x;
    int warpId = tid >> 5, lane = tid & 31;
    int og = lane & 7, pxs = lane >> 3;
    int px0 = (warpId << 2) | pxs;      // second pixel = px0 + 16
    int og16 = og << 4;                 // byte offset within a 128B row
    int og8 = og << 3;

    ull acc[2][4];
#pragma unroll
    for (int p = 0; p < 2; p++)
#pragma unroll
        for (int j = 0; j < 4; j++) acc[p][j] = 0ull;

    const char* swbr = (const char*)g_swh + br * 1327104 + og16;
    const float* bwbr = g_bwt + br * 36864 + og8;
    const float* xb = x + b * 64 * 4096;

#pragma unroll 1
    for (int i = 0; i < 64; i++) {
        // ---- stage taps for channel i ----
        for (int j = tid; j < 288; j += 128) {
            int k = j >> 5, p = j & 31;
            int ki = k / 3, kj = k - ki * 3;
            int hh = h + (ki - 1) * d;
            int ww = w0 + p + (kj - 1) * d;
            float v = 0.f;
            if ((unsigned)hh < 64u && (unsigned)ww < 64u)
                v = xb[i * 4096 + hh * 64 + ww];
            float e = __expf(-v);
            float silu = __fdividef(v, 1.f + e);
            float s = fmaf(v, invh, s0);
            float mf = floorf(s);
            float u = s - mf;
            float msk = (s >= 0.f && s < smax) ? (1.f / 6.f) : 0.f;
            int mi = (int)mf;
            mi = min(max(mi, 0), G + 5);
            float u2 = u * u, u3 = u2 * u;
            float omu = 1.f - u;
            float c0 = omu * omu * omu * msk;
            float c3 = u3 * msk;
            float c1 = (3.f * u3 - 6.f * u2 + 4.f) * msk;
            float c2 = (-3.f * u3 + 3.f * u2 + 3.f * u + 1.f) * msk;
            sSil[k][p] = make_float2(silu, silu);
            sOff[k][p] = mi << 7;                 // mi*128 bytes
            sCh[k][p] = make_uint4(h2u(__floats2half2_rn(c0, c0)),
                                   h2u(__floats2half2_rn(c1, c1)),
                                   h2u(__floats2half2_rn(c2, c2)),
                                   h2u(__floats2half2_rn(c3, c3)));
        }
        __syncthreads();

        const char* swi = swbr + i * 20736;      // 9*18*64*2 bytes
        const float* bwi = bwbr + i * 576;
#pragma unroll 1
        for (int k = 0; k < 9; k++) {
            // base weights as natural f32 pairs (o even/odd adjacent)
            const ulonglong2* bwp = (const ulonglong2*)(bwi + (k << 6));
            ulonglong2 bwA = bwp[0];
            ulonglong2 bwB = bwp[1];
            ull bw[4] = {bwA.x, bwA.y, bwB.x, bwB.y};
            const char* swk = swi + k * 2304;    // 18*64*2 bytes
#pragma unroll
            for (int pp = 0; pp < 2; pp++) {
                int px = px0 + (pp << 4);
                ull sil = *(const ull*)&sSil[k][px];   // LDS.64 -> aligned pair
                int off = sOff[k][px];
                uint4 ch = sCh[k][px];
                const char* wp = swk + off;
                uint4 r0 = *(const uint4*)(wp);
                uint4 r1 = *(const uint4*)(wp + 128);
                uint4 r2 = *(const uint4*)(wp + 256);
                uint4 r3 = *(const uint4*)(wp + 384);
                __half2 c0h = u2h(ch.x), c1h = u2h(ch.y), c2h = u2h(ch.z), c3h = u2h(ch.w);
                const unsigned* q0 = (const unsigned*)&r0;
                const unsigned* q1 = (const unsigned*)&r1;
                const unsigned* q2 = (const unsigned*)&r2;
                const unsigned* q3 = (const unsigned*)&r3;
#pragma unroll
                for (int j = 0; j < 4; j++) {
                    __half2 pt = __hmul2(c0h, u2h(q0[j]));
                    pt = __hfma2(c1h, u2h(q1[j]), pt);
                    pt = __hfma2(c2h, u2h(q2[j]), pt);
                    pt = __hfma2(c3h, u2h(q3[j]), pt);
                    ull a = fadd2u(acc[pp][j], h2f2(h2u(pt)));
                    acc[pp][j] = ffma2u(sil, bw[j], a);
                }
            }
        }
        __syncthreads();
    }

    // store: 2 px x 8 o scalar stores (negligible vs inner-loop traffic)
    int zbase = z * 64;
#pragma unroll
    for (int pp = 0; pp < 2; pp++) {
        int hw = h * 64 + w0 + px0 + (pp << 4);
#pragma unroll
        for (int j = 0; j < 4; j++) {
            float2 v = unpack2(acc[pp][j]);
            int o = og8 + (j << 1);
            g_ybr[(zbase + o) * 4096 + hw] = v.x;
            g_ybr[(zbase + o + 1) * 4096 + hw] = v.y;
        }
    }
}

// ---------------- per-branch BN stats (mean/var over batch+spatial) ----------------
__global__ void bnstats_kernel(const float* __restrict__ g6, const float* __restrict__ bb6,
                               const float* __restrict__ g12, const float* __restrict__ bb12,
                               const float* __restrict__ g18, const float* __restrict__ bb18) {
    __shared__ float sbuf[256];
    int o = blockIdx.x, br = blockIdx.y;
    const float4* p0 = (const float4*)(g_ybr + ((br * 2 + 0) * 64 + o) * 4096);
    const float4* p1 = (const float4*)(g_ybr + ((br * 2 + 1) * 64 + o) * 4096);
    float s = 0.f, sq = 0.f;
    for (int j = threadIdx.x; j < 1024; j += 256) {
        float4 v0 = p0[j], v1 = p1[j];
        s += (v0.x + v0.y) + (v0.z + v0.w) + (v1.x + v1.y) + (v1.z + v1.w);
        sq += v0.x * v0.x + v0.y * v0.y + v0.z * v0.z + v0.w * v0.w
            + v1.x * v1.x + v1.y * v1.y + v1.z * v1.z + v1.w * v1.w;
    }
    s = block_reduce(s, sbuf);
    sq = block_reduce(sq, sbuf);
    if (threadIdx.x == 0) {
        float mean = s * (1.f / 8192.f);
        float var = sq * (1.f / 8192.f) - mean * mean;
        const float* gg = (br == 0) ? g6 : ((br == 1) ? g12 : g18);
        const float* bb = (br == 0) ? bb6 : ((br == 1) ? bb12 : bb18);
        float a = gg[o] * rsqrtf(var + BN_EPS);
        g_bna[br * 64 + o] = a;
        g_bnc[br * 64 + o] = bb[o] - mean * a;
    }
}

// ---------------- SE spatial reduce: mean over hw of relu(bn(y)) ----------------
__global__ void sered_kernel() {
    __shared__ float sbuf[128];
    int o = blockIdx.x, b = blockIdx.y, br = blockIdx.z;
    const float4* p = (const float4*)(g_ybr + ((br * 2 + b) * 64 + o) * 4096);
    float a = g_bna[br * 64 + o], c = g_bnc[br * 64 + o];
    float s = 0.f;
    for (int j = threadIdx.x; j < 1024; j += 128) {
        float4 v = p[j];
        s += fmaxf(fmaf(v.x, a, c), 0.f) + fmaxf(fmaf(v.y, a, c), 0.f)
           + fmaxf(fmaf(v.z, a, c), 0.f) + fmaxf(fmaf(v.w, a, c), 0.f);
    }
    s = block_reduce(s, sbuf);
    if (threadIdx.x == 0) g_sered[(br * 2 + b) * 64 + o] = s * (1.f / 4096.f);
}

// ---------------- SE MLPs + full gp branch + gp fuse term (one CTA) ----------------
__global__ void small_kernel(const float* __restrict__ w1_0, const float* __restrict__ w2_0,
                             const float* __restrict__ w1_1, const float* __restrict__ w2_1,
                             const float* __restrict__ w1_2, const float* __restrict__ w2_2,
                             const float* __restrict__ gpw, const float* __restrict__ gpb,
                             const float* __restrict__ gpg, const float* __restrict__ gpbeta,
                             const float* __restrict__ gpse1, const float* __restrict__ gpse2,
                             const float* __restrict__ fw) {
    __shared__ float sT[24];
    __shared__ float sGp0[128];
    __shared__ float sZ[128];
    __shared__ float sT2[8];
    __shared__ float sGpv[128];
    int tid = threadIdx.x;

    if (tid < 24) {
        int br = tid >> 3;
        int rem = tid & 7;
        int b = rem >> 2, j = rem & 3;
        const float* w1 = (br == 0) ? w1_0 : ((br == 1) ? w1_1 : w1_2);
        float v = 0.f;
        for (int o2 = 0; o2 < 64; o2++) v += g_sered[(br * 2 + b) * 64 + o2] * w1[j * 64 + o2];
        sT[tid] = fmaxf(v, 0.f);
    }
    {
        int b = tid >> 6, o = tid & 63;
        float v = gpb[o];
        for (int i = 0; i < 64; i++) v += g_xmean[b * 64 + i] * gpw[o * 64 + i];
        sGp0[tid] = v;
    }
    __syncthreads();

    if (tid < 64) {
        int o = tid;
        for (int br = 0; br < 3; br++) {
            const float* w2 = (br == 0) ? w2_0 : ((br == 1) ? w2_1 : w2_2);
            for (int b = 0; b < 2; b++) {
                float v = 0.f;
                for (int j = 0; j < 4; j++) v += sT[br * 8 + b * 4 + j] * w2[o * 4 + j];
                g_scale[(br * 2 + b) * 64 + o] = sigmoidf_(v);
            }
        }
        float a0 = sGp0[o], a1 = sGp0[64 + o];
        float m = 0.5f * (a0 + a1);
        float dv = a0 - m;
        float var = dv * dv;
        float rs = gpg[o] * rsqrtf(var + BN_EPS);
        sZ[o]      = fmaxf((a0 - m) * rs + gpbeta[o], 0.f);
        sZ[64 + o] = fmaxf((a1 - m) * rs + gpbeta[o], 0.f);
    }
    __syncthreads();

    if (tid < 8) {
        int b = tid >> 2, j = tid & 3;
        float v = 0.f;
        for (int o2 = 0; o2 < 64; o2++) v += sZ[b * 64 + o2] * gpse1[j * 64 + o2];
        sT2[tid] = fmaxf(v, 0.f);
    }
    __syncthreads();

    {
        int b = tid >> 6, o = tid & 63;
        float v = 0.f;
        for (int j = 0; j < 4; j++) v += sT2[b * 4 + j] * gpse2[o * 4 + j];
        sGpv[tid] = sZ[tid] * sigmoidf_(v);
    }
    __syncthreads();

    {
        int b = tid >> 6, oo = tid & 63;
        float v = 0.f;
        for (int i = 0; i < 64; i++) v += fw[oo * 256 + 192 + i] * sGpv[b * 64 + i];
        g_gpterm[tid] = v;
    }
}

// ---------------- fuse 1x1 conv over the 192 branch channels ----------------
__global__ void __launch_bounds__(128) fuse_kernel(const float* __restrict__ fuse_b) {
    __shared__ float sCat[192][32];
    int b = blockIdx.z, h = blockIdx.y, w0 = blockIdx.x << 5;
    int tid = threadIdx.x;

    for (int j = tid; j < 1536; j += 128) {   // 192 ch x 8 float4
        int ch = j >> 3, p4 = (j & 7) << 2;
        int br = ch >> 6, i = ch & 63;
        float4 v = *(const float4*)(g_ybr + ((br * 2 + b) * 64 + i) * 4096 + h * 64 + w0 + p4);
        float a = g_bna[br * 64 + i], c = g_bnc[br * 64 + i];
        float sc = g_scale[(br * 2 + b) * 64 + i];
        float4 r;
        r.x = fmaxf(fmaf(v.x, a, c), 0.f) * sc;
        r.y = fmaxf(fmaf(v.y, a, c), 0.f) * sc;
        r.z = fmaxf(fmaf(v.z, a, c), 0.f) * sc;
        r.w = fmaxf(fmaf(v.w, a, c), 0.f) * sc;
        *(float4*)&sCat[ch][p4] = r;
    }
    __syncthreads();

    int warpId = tid >> 5, lane = tid & 31;
    int o = ((warpId & 1) << 5) | lane;
    int ph = warpId >> 1;
    float acc[16];
    float init = g_gpterm[b * 64 + o] + fuse_b[o];
#pragma unroll
    for (int p = 0; p < 16; p++) acc[p] = init;

#pragma unroll 1
    for (int ch = 0; ch < 192; ch++) {
        float fwv = g_fwt[(ch << 6) + o];
#pragma unroll
        for (int p = 0; p < 16; p++)
            acc[p] = fmaf(fwv, sCat[ch][(ph << 4) + p], acc[p]);
    }

    int base = (b * 64 + o) * 4096 + h * 64 + w0 + (ph << 4);
#pragma unroll
    for (int p = 0; p < 16; p++) g_out0[base + p] = acc[p];
}

// ---------------- fuse BN stats ----------------
__global__ void fstats_kernel(const float* __restrict__ fg, const float* __restrict__ fb) {
    __shared__ float sbuf[256];
    int o = blockIdx.x;
    const float4* p0 = (const float4*)(g_out0 + o * 4096);
    const float4* p1 = (const float4*)(g_out0 + (64 + o) * 4096);
    float s = 0.f, sq = 0.f;
    for (int j = threadIdx.x; j < 1024; j += 256) {
        float4 v0 = p0[j], v1 = p1[j];
        s += (v0.x + v0.y) + (v0.z + v0.w) + (v1.x + v1.y) + (v1.z + v1.w);
        sq += v0.x * v0.x + v0.y * v0.y + v0.z * v0.z + v0.w * v0.w
            + v1.x * v1.x + v1.y * v1.y + v1.z * v1.z + v1.w * v1.w;
    }
    s = block_reduce(s, sbuf);
    sq = block_reduce(sq, sbuf);
    if (threadIdx.x == 0) {
        float mean = s * (1.f / 8192.f);
        float var = sq * (1.f / 8192.f) - mean * mean;
        float a = fg[o] * rsqrtf(var + BN_EPS);
        g_fa[o] = a;
        g_fc[o] = fb[o] - mean * a;
    }
}

// ---------------- final elementwise: relu(bn(fuse_out)) ----------------
__global__ void final_kernel(float* __restrict__ out) {
    int idx = blockIdx.x * blockDim.x + threadIdx.x;
    if (idx >= 131072) return;
    int o = (idx >> 10) & 63;
    float a = g_fa[o], c = g_fc[o];
    float4 v = ((const float4*)g_out0)[idx];
    float4 r;
    r.x = fmaxf(fmaf(v.x, a, c), 0.f);
    r.y = fmaxf(fmaf(v.y, a, c), 0.f);
    r.z = fmaxf(fmaf(v.z, a, c), 0.f);
    r.w = fmaxf(fmaf(v.w, a, c), 0.f);
    ((float4*)out)[idx] = r;
}

// ---------------- launch ----------------
extern "C" void kernel_launch(void* const* d_in, const int* in_sizes, int n_in,
                              void* d_out, int out_size) {
    const float* x       = (const float*)d_in[0];
    const float* bw6     = (const float*)d_in[1];
    const float* sw6     = (const float*)d_in[2];
    const float* bn6_g   = (const float*)d_in[3];
    const float* bn6_b   = (const float*)d_in[4];
    const float* se6_w1  = (const float*)d_in[5];
    const float* se6_w2  = (const float*)d_in[6];
    const float* bw12    = (const float*)d_in[7];
    const float* sw12    = (const float*)d_in[8];
    const float* bn12_g  = (const float*)d_in[9];
    const float* bn12_b  = (const float*)d_in[10];
    const float* se12_w1 = (const float*)d_in[11];
    const float* se12_w2 = (const float*)d_in[12];
    const float* bw18    = (const float*)d_in[13];
    const float* sw18    = (const float*)d_in[14];
    const float* bn18_g  = (const float*)d_in[15];
    const float* bn18_b  = (const float*)d_in[16];
    const float* se18_w1 = (const float*)d_in[17];
    const float* se18_w2 = (const float*)d_in[18];
    const float* gp_w    = (const float*)d_in[19];
    const float* gp_b    = (const float*)d_in[20];
    const float* gp_bn_g = (const float*)d_in[21];
    const float* gp_bn_b = (const float*)d_in[22];
    const float* gp_se1  = (const float*)d_in[23];
    const float* gp_se2  = (const float*)d_in[24];
    const float* fuse_w  = (const float*)d_in[25];
    const float* fuse_b  = (const float*)d_in[26];
    const float* fbn_g   = (const float*)d_in[27];
    const float* fbn_b   = (const float*)d_in[28];
    float* out = (float*)d_out;

    pack_kernel<<<512, 256>>>(bw6, sw6, bw12, sw12, bw18, sw18, fuse_w);
    xmean_kernel<<<128, 128>>>(x);
    conv_kernel<<<dim3(2, 64, 6), 128>>>(x);
    bnstats_kernel<<<dim3(64, 3), 256>>>(bn6_g, bn6_b, bn12_g, bn12_b, bn18_g, bn18_b);
    sered_kernel<<<dim3(64, 2, 3), 128>>>();
    small_kernel<<<1, 128>>>(se6_w1, se6_w2, se12_w1, se12_w2, se18_w1, se18_w2,
                             gp_w, gp_b, gp_bn_g, gp_bn_b, gp_se1, gp_se2, fuse_w);
    fuse_kernel<<<dim3(2, 64, 2), 128>>>(fuse_b);
    fstats_kernel<<<64, 256>>>(fbn_g, fbn_b);
    final_kernel<<<512, 256>>>(out);
}